// round 15
// baseline (speedup 1.0000x reference)
#include <cuda_runtime.h>
#include <cuda_fp16.h>
#include <math.h>
#include <stdint.h>

#define BB   32
#define SEQ  197
#define DIM  768
#define NHD  12
#define HD   64
#define NL   12
#define NCLS 1000
#define MLPD 3072
#define NTOK (BB*SEQ)     // 6304
#define NPAT 196
#define MT128 ((NTOK+127)/128)   // 50 M-tiles of 128

// -------------------- scratch (device globals; no allocation allowed) -----
__device__ float g_X[NTOK*DIM];
__device__ float g_Q[NTOK*DIM];
__device__ float g_K[NTOK*DIM];
__device__ float g_V[NTOK*DIM];
// activations as pre-split fp16 hi/lo (stored as uint32 words = half2 pairs)
__device__ uint32_t g_Hhw[NTOK*DIM/2],  g_Hlw[NTOK*DIM/2];
__device__ uint32_t g_Ahw[BB*NPAT*DIM/2], g_Alw[BB*NPAT*DIM/2];
__device__ uint32_t g_Uhw[(size_t)NTOK*MLPD/2], g_Ulw[(size_t)NTOK*MLPD/2];
// weights pre-split, kpair-interleaved words: w[kp][n] = half2(B[2kp][n], B[2kp+1][n])
__device__ uint32_t g_Wph[(DIM/2)*DIM],          g_Wpl[(DIM/2)*DIM];
__device__ uint32_t g_W1h[(size_t)NL*(DIM/2)*MLPD], g_W1l[(size_t)NL*(DIM/2)*MLPD];
__device__ uint32_t g_W2h[(size_t)NL*(MLPD/2)*DIM], g_W2l[(size_t)NL*(MLPD/2)*DIM];
__device__ uint32_t g_Wqh[NL*NHD*(HD/2)*HD], g_Wql[NL*NHD*(HD/2)*HD];
__device__ uint32_t g_Wkh[NL*NHD*(HD/2)*HD], g_Wkl[NL*NHD*(HD/2)*HD];
__device__ uint32_t g_Wvh[NL*NHD*(HD/2)*HD], g_Wvl[NL*NHD*(HD/2)*HD];

// -------------------- helpers --------------------------------------------
__device__ __forceinline__ void split2(float x, float y, uint32_t& hw, uint32_t& lw)
{
    __half2 h = __floats2half2_rn(x, y);
    float2 hf = __half22float2(h);
    __half2 l = __floats2half2_rn(x - hf.x, y - hf.y);
    hw = *(uint32_t*)&h;
    lw = *(uint32_t*)&l;
}

__device__ __forceinline__ void split1(float x, __half* hp, __half* lp)
{
    __half h = __float2half_rn(x);
    *hp = h;
    *lp = __float2half_rn(x - __half2float(h));
}

// -------------------- weight pre-split ------------------------------------
// src: f32 [Krows x N] row-major; dst: words [Krows/2 x N]
__global__ void presplit_b(const float* __restrict__ src,
                           uint32_t* __restrict__ dh, uint32_t* __restrict__ dl,
                           int N)
{
    int n = blockIdx.x*blockDim.x + threadIdx.x;
    if (n >= N) return;
    int kp = blockIdx.y;
    float x0 = src[(size_t)(2*kp)*N + n];
    float x1 = src[(size_t)(2*kp+1)*N + n];
    uint32_t h, l;
    split2(x0, x1, h, l);
    dh[(size_t)kp*N + n] = h;
    dl[(size_t)kp*N + n] = l;
}

// -------------------- patchify: images -> hi/lo half tokens ---------------
__global__ void patchify_kernel(const float* __restrict__ img)
{
    int idx = blockIdx.x*256 + threadIdx.x;
    const int total = BB*NPAT*DIM;
    if (idx >= total) return;
    int f = idx % DIM;
    int p = (idx / DIM) % NPAT;
    int b = idx / (DIM*NPAT);
    int c = f >> 8;
    int rem = f & 255;
    int i = rem >> 4;
    int j = rem & 15;
    int pr = p / 14, pc = p % 14;
    float v = img[(((size_t)b*3 + c)*224 + (pr*16+i))*224 + (pc*16+j)];
    split1(v, (__half*)g_Ahw + idx, (__half*)g_Alw + idx);
}

// -------------------- assemble tokens: cls + embed + pos -> X -------------
// embed GEMM wrote f32 patch tokens into g_Q
__global__ void assemble_kernel(const float* __restrict__ cls,
                                const float* __restrict__ pos)
{
    int idx = blockIdx.x*256 + threadIdx.x;
    if (idx >= NTOK*DIM) return;
    int d = idx % DIM;
    int s = (idx / DIM) % SEQ;
    int b = idx / (DIM*SEQ);
    float v = (s == 0) ? cls[d] : g_Q[((size_t)b*NPAT + (s-1))*DIM + d];
    g_X[idx] = v + pos[s*DIM + d];
}

// ==================== FP16x3 mma.sync GEMM, pre-split operands ============
// 128x64 C-tile, 256 threads (8 warps 4x2), warp tile 32x32, BK=32.
// A: hi/lo half arrays, row-major (lda halves). B: hi/lo kpair-word arrays
// (ldbw words). Double-buffered smem, one barrier per K-iter, pure-copy loads.
// EPI 0: C_f32 = acc+bias ; 1: (Ch,Cl) = split(gelu(acc+bias)) ; 2: C_f32 += acc+bias

#define AWS 20
#define BWS 72
#define A_ST (128*AWS)          // 2560 words per stage per array
#define B_ST (16*BWS)           // 1152
#define OFF_AH 0
#define OFF_AL (2*A_ST)         // 5120
#define OFF_BH (4*A_ST)         // 10240
#define OFF_BL (4*A_ST + 2*B_ST)
#define GEMM_WORDS (4*A_ST + 4*B_ST)   // 14848
#define GEMM_SMEM (GEMM_WORDS*4)       // 59392

__device__ __forceinline__ void mma_f16(float* cc, const uint32_t* a, const uint32_t* b)
{
    asm volatile(
        "mma.sync.aligned.m16n8k16.row.col.f32.f16.f16.f32 "
        "{%0,%1,%2,%3}, {%4,%5,%6,%7}, {%8,%9}, {%0,%1,%2,%3};\n"
        : "+f"(cc[0]), "+f"(cc[1]), "+f"(cc[2]), "+f"(cc[3])
        : "r"(a[0]), "r"(a[1]), "r"(a[2]), "r"(a[3]),
          "r"(b[0]), "r"(b[1]));
}

template<int EPI>
__device__ __forceinline__ void gemm16_tile(
    const __half* __restrict__ Ah, const __half* __restrict__ Al, int lda,
    const uint32_t* __restrict__ Bh, const uint32_t* __restrict__ Bl, int ldbw,
    const float* __restrict__ bias,
    float* __restrict__ C, uint32_t* __restrict__ Ch, uint32_t* __restrict__ Cl,
    int ldc, int M, int K, int m0, int n0)
{
    extern __shared__ uint32_t smw[];

    int tid  = threadIdx.x;
    int lane = tid & 31, wid = tid >> 5;
    int warpM = wid >> 1, warpN = wid & 1;
    int g = lane >> 2, c = lane & 3;

    // loader mapping
    int arow = tid >> 2, aq = tid & 3;     // A: rows arow, arow+64; uint4 slot aq
    int bkp  = tid >> 4, bq = tid & 15;    // B: kpair bkp; uint4 slot bq

    float acc[2][4][4] = {};
    uint4 rah[2], ral[2], rbh, rbl;

    // ---- prologue: LDG chunk 0 ----
#pragma unroll
    for (int i = 0; i < 2; i++) {
        int gm = m0 + arow + i*64;
        if (gm < M) {
            rah[i] = *(const uint4*)&Ah[(size_t)gm*lda + aq*8];
            ral[i] = *(const uint4*)&Al[(size_t)gm*lda + aq*8];
        } else {
            rah[i] = make_uint4(0,0,0,0);
            ral[i] = make_uint4(0,0,0,0);
        }
    }
    rbh = *(const uint4*)&Bh[(size_t)bkp*ldbw + n0 + bq*4];
    rbl = *(const uint4*)&Bl[(size_t)bkp*ldbw + n0 + bq*4];

    int p = 0;
    for (int k0 = 0; k0 < K; k0 += 32) {
        // ---- STS staged chunk into buffer p ----
        uint32_t* AH = smw + OFF_AH + p*A_ST;
        uint32_t* AL = smw + OFF_AL + p*A_ST;
        uint32_t* BH = smw + OFF_BH + p*B_ST;
        uint32_t* BL = smw + OFF_BL + p*B_ST;
#pragma unroll
        for (int i = 0; i < 2; i++) {
            int row = arow + i*64;
            *(uint4*)&AH[row*AWS + aq*4] = rah[i];
            *(uint4*)&AL[row*AWS + aq*4] = ral[i];
        }
        *(uint4*)&BH[bkp*BWS + bq*4] = rbh;
        *(uint4*)&BL[bkp*BWS + bq*4] = rbl;
        __syncthreads();

        // ---- prefetch next chunk ----
        if (k0 + 32 < K) {
            int kn = k0 + 32;
#pragma unroll
            for (int i = 0; i < 2; i++) {
                int gm = m0 + arow + i*64;
                if (gm < M) {
                    rah[i] = *(const uint4*)&Ah[(size_t)gm*lda + kn + aq*8];
                    ral[i] = *(const uint4*)&Al[(size_t)gm*lda + kn + aq*8];
                } else {
                    rah[i] = make_uint4(0,0,0,0);
                    ral[i] = make_uint4(0,0,0,0);
                }
            }
            rbh = *(const uint4*)&Bh[(size_t)(kn/2 + bkp)*ldbw + n0 + bq*4];
            rbl = *(const uint4*)&Bl[(size_t)(kn/2 + bkp)*ldbw + n0 + bq*4];
        }

        // ---- compute from buffer p: 2 k16 steps ----
#pragma unroll
        for (int kk = 0; kk < 2; kk++) {
            int ko = kk*8;
            uint32_t ah[2][4], al[2][4];
#pragma unroll
            for (int mt = 0; mt < 2; mt++) {
                int r = warpM*32 + mt*16 + g;
                ah[mt][0] = AH[ r   *AWS + ko + c];
                ah[mt][1] = AH[(r+8)*AWS + ko + c];
                ah[mt][2] = AH[ r   *AWS + ko + c + 4];
                ah[mt][3] = AH[(r+8)*AWS + ko + c + 4];
                al[mt][0] = AL[ r   *AWS + ko + c];
                al[mt][1] = AL[(r+8)*AWS + ko + c];
                al[mt][2] = AL[ r   *AWS + ko + c + 4];
                al[mt][3] = AL[(r+8)*AWS + ko + c + 4];
            }
            uint32_t bh[4][2], bl[4][2];
#pragma unroll
            for (int nt = 0; nt < 4; nt++) {
                int ncol = warpN*32 + nt*8 + g;
                bh[nt][0] = BH[(ko + c    )*BWS + ncol];
                bh[nt][1] = BH[(ko + c + 4)*BWS + ncol];
                bl[nt][0] = BL[(ko + c    )*BWS + ncol];
                bl[nt][1] = BL[(ko + c + 4)*BWS + ncol];
            }
#pragma unroll
            for (int mt = 0; mt < 2; mt++)
#pragma unroll
                for (int nt = 0; nt < 4; nt++) {
                    mma_f16(acc[mt][nt], ah[mt], bl[nt]);
                    mma_f16(acc[mt][nt], al[mt], bh[nt]);
                    mma_f16(acc[mt][nt], ah[mt], bh[nt]);
                }
        }
        p ^= 1;
    }

    // ---- epilogue ----
    int ldcw = ldc >> 1;
#pragma unroll
    for (int mt = 0; mt < 2; mt++) {
#pragma unroll
        for (int nt = 0; nt < 4; nt++) {
            int r0  = m0 + warpM*32 + mt*16 + g;
            int col = n0 + warpN*32 + nt*8 + 2*c;
#pragma unroll
            for (int half = 0; half < 2; half++) {
                int gm = r0 + half*8;
                if (gm >= M) continue;
                float v0 = acc[mt][nt][half*2 + 0] + bias[col];
                float v1 = acc[mt][nt][half*2 + 1] + bias[col+1];
                if (EPI == 1) {
                    v0 = 0.5f*v0*(1.f + erff(v0*0.70710678118654752f));
                    v1 = 0.5f*v1*(1.f + erff(v1*0.70710678118654752f));
                    uint32_t hw, lw;
                    split2(v0, v1, hw, lw);
                    Ch[(size_t)gm*ldcw + (col>>1)] = hw;
                    Cl[(size_t)gm*ldcw + (col>>1)] = lw;
                } else {
                    float* cp = &C[(size_t)gm*ldc + col];
                    if (EPI == 2) { v0 += cp[0]; v1 += cp[1]; }
                    cp[0] = v0;
                    cp[1] = v1;
                }
            }
        }
    }
}

template<int EPI>
__global__ __launch_bounds__(256) void gemm16_kernel(
    const __half* __restrict__ Ah, const __half* __restrict__ Al, int lda,
    const uint32_t* __restrict__ Bh, const uint32_t* __restrict__ Bl, int ldbw,
    const float* __restrict__ bias,
    float* __restrict__ C, uint32_t* __restrict__ Ch, uint32_t* __restrict__ Cl,
    int ldc, int M, int K)
{
    gemm16_tile<EPI>(Ah, Al, lda, Bh, Bl, ldbw, bias, C, Ch, Cl, ldc, M, K,
                     blockIdx.y*128, blockIdx.x*64);
}

// per-head QKV. grid: (1, Mtiles128, 36 = 12 heads x 3 types)
__global__ __launch_bounds__(256) void qkv_kernel(
    const float* __restrict__ bq, const float* __restrict__ bk,
    const float* __restrict__ bv, int layer)
{
    int z = blockIdx.z;
    int h = z % NHD, t = z / NHD;
    const uint32_t *Bh, *Bl; const float* bi; float* C;
    if (t == 0)      { Bh = g_Wqh; Bl = g_Wql; bi = bq; C = g_Q; }
    else if (t == 1) { Bh = g_Wkh; Bl = g_Wkl; bi = bk; C = g_K; }
    else             { Bh = g_Wvh; Bl = g_Wvl; bi = bv; C = g_V; }
    size_t off = (size_t)layer*NHD + h;
    gemm16_tile<0>((const __half*)g_Hhw + h*HD, (const __half*)g_Hlw + h*HD, DIM,
                   Bh + off*(HD/2)*HD, Bl + off*(HD/2)*HD, HD,
                   bi + off*HD,
                   C + h*HD, 0, 0, DIM,
                   NTOK, HD, blockIdx.y*128, 0);
}

// -------------------- layernorm -> hi/lo halves ---------------------------
__global__ __launch_bounds__(256) void ln_kernel(
    const float* __restrict__ X,
    const float* __restrict__ gw, const float* __restrict__ bw)
{
    __shared__ float rs[8], rq[8];
    int row = blockIdx.x, tid = threadIdx.x;
    int lane = tid & 31, wid = tid >> 5;
    const float* x = X + (size_t)row*DIM;
    float v0 = x[tid], v1 = x[tid+256], v2 = x[tid+512];
    float s = v0+v1+v2;
    float q = v0*v0 + v1*v1 + v2*v2;
#pragma unroll
    for (int o = 16; o; o >>= 1) {
        s += __shfl_xor_sync(0xffffffffu, s, o);
        q += __shfl_xor_sync(0xffffffffu, q, o);
    }
    if (lane == 0) { rs[wid] = s; rq[wid] = q; }
    __syncthreads();
    if (tid == 0) {
        float ts = 0.f, tq = 0.f;
        for (int w = 0; w < 8; w++) { ts += rs[w]; tq += rq[w]; }
        rs[0] = ts; rq[0] = tq;
    }
    __syncthreads();
    float mean = rs[0]*(1.0f/DIM);
    float var  = rq[0]*(1.0f/DIM) - mean*mean;
    float inv  = rsqrtf(var + 1e-5f);
    __half* Hh = (__half*)g_Hhw + (size_t)row*DIM;
    __half* Hl = (__half*)g_Hlw + (size_t)row*DIM;
    float y0 = (v0-mean)*inv*gw[tid]     + bw[tid];
    float y1 = (v1-mean)*inv*gw[tid+256] + bw[tid+256];
    float y2 = (v2-mean)*inv*gw[tid+512] + bw[tid+512];
    split1(y0, Hh+tid,     Hl+tid);
    split1(y1, Hh+tid+256, Hl+tid+256);
    split1(y2, Hh+tid+512, Hl+tid+512);
}

// -------------------- attention: warp-parallel queries --------------------
#define PSTR 208
#define ATTN_SMEM_FLOATS (2*SEQ*HD + 4*HD + 4*PSTR)
#define ATTN_SMEM_BYTES  (ATTN_SMEM_FLOATS*4)

__global__ __launch_bounds__(128) void attn_kernel(
    const float* __restrict__ Q, const float* __restrict__ K,
    const float* __restrict__ V, float* __restrict__ X)
{
    extern __shared__ float sm[];
    float* Ks = sm;
    float* Vs = Ks + SEQ*HD;
    float* qs = Vs + SEQ*HD;
    float* ps = qs + 4*HD;

    int bh = blockIdx.x;
    int b = bh / NHD, h = bh % NHD;
    int tid = threadIdx.x;
    int lane = tid & 31, wid = tid >> 5;
    size_t base = (size_t)b*SEQ*DIM + (size_t)h*HD;

    for (int idx = tid; idx < SEQ*32; idx += 128) {
        int t = idx >> 5, e2 = idx & 31;
        ((float2*)Ks)[idx] = *(const float2*)&K[base + (size_t)t*DIM + 2*e2];
        ((float2*)Vs)[idx] = *(const float2*)&V[base + (size_t)t*DIM + 2*e2];
    }
    __syncthreads();

    float* myq = qs + wid*HD;
    float* myp = ps + wid*PSTR;
    const float2* q2 = (const float2*)myq;
    const float2* vr = (const float2*)Vs;

    for (int s = wid; s < SEQ; s += 4) {
        *(float2*)&myq[2*lane] = *(const float2*)&Q[base + (size_t)s*DIM + 2*lane];
        __syncwarp();

        float lm = -1e30f;
        for (int j = lane; j < SEQ; j += 32) {
            const float2* kr = (const float2*)&Ks[j*HD];
            float d = 0.f;
#pragma unroll
            for (int e2 = 0; e2 < 32; e2++) {
                int ee = (e2 + lane) & 31;
                float2 kv = kr[ee];
                float2 qv = q2[ee];
                d = fmaf(qv.x, kv.x, d);
                d = fmaf(qv.y, kv.y, d);
            }
            d *= 0.125f;
            myp[j] = d;
            lm = fmaxf(lm, d);
        }
#pragma unroll
        for (int o = 16; o; o >>= 1)
            lm = fmaxf(lm, __shfl_xor_sync(0xffffffffu, lm, o));

        float ls = 0.f;
        for (int j = lane; j < SEQ; j += 32) {
            float e = expf(myp[j] - lm);
            myp[j] = e;
            ls += e;
        }
#pragma unroll
        for (int o = 16; o; o >>= 1)
            ls += __shfl_xor_sync(0xffffffffu, ls, o);
        float inv = 1.f / ls;
        __syncwarp();

        float2 acc = make_float2(0.f, 0.f);
        int t = 0;
        for (; t + 4 <= SEQ; t += 4) {
#pragma unroll
            for (int u = 0; u < 4; u++) {
                float p = myp[t+u];
                float2 vv = vr[(t+u)*32 + lane];
                acc.x = fmaf(p, vv.x, acc.x);
                acc.y = fmaf(p, vv.y, acc.y);
            }
        }
        for (; t < SEQ; t++) {
            float p = myp[t];
            float2 vv = vr[t*32 + lane];
            acc.x = fmaf(p, vv.x, acc.x);
            acc.y = fmaf(p, vv.y, acc.y);
        }

        float* xp = &X[base + (size_t)s*DIM + 2*lane];
        float2 xo = *(float2*)xp;
        xo.x += acc.x * inv;
        xo.y += acc.y * inv;
        *(float2*)xp = xo;
        __syncwarp();
    }
}

// -------------------- classifier head + softmax ---------------------------
__global__ __launch_bounds__(256) void head_kernel(
    const float* __restrict__ X, const float* __restrict__ Wh,
    const float* __restrict__ bh, float* __restrict__ out)
{
    __shared__ float xr[DIM];
    __shared__ float lg[NCLS];
    __shared__ float red[8];
    int b = blockIdx.x, tid = threadIdx.x;
    int lane = tid & 31, wid = tid >> 5;

    for (int d = tid; d < DIM; d += 256) xr[d] = X[(size_t)b*SEQ*DIM + d];
    __syncthreads();

    for (int n = tid; n < NCLS; n += 256) {
        float a = bh[n];
        for (int k = 0; k < DIM; k++)
            a = fmaf(xr[k], Wh[(size_t)k*NCLS + n], a);
        lg[n] = a;
    }
    __syncthreads();

    float lm = -1e30f;
    for (int n = tid; n < NCLS; n += 256) lm = fmaxf(lm, lg[n]);
#pragma unroll
    for (int o = 16; o; o >>= 1) lm = fmaxf(lm, __shfl_xor_sync(0xffffffffu, lm, o));
    if (lane == 0) red[wid] = lm;
    __syncthreads();
    if (tid == 0) {
        float m = red[0];
        for (int w = 1; w < 8; w++) m = fmaxf(m, red[w]);
        red[0] = m;
    }
    __syncthreads();
    float mx = red[0];

    float ls = 0.f;
    for (int n = tid; n < NCLS; n += 256) {
        float e = expf(lg[n] - mx);
        lg[n] = e;
        ls += e;
    }
#pragma unroll
    for (int o = 16; o; o >>= 1) ls += __shfl_xor_sync(0xffffffffu, ls, o);
    __syncthreads();
    if (lane == 0) red[wid] = ls;
    __syncthreads();
    if (tid == 0) {
        float s2 = 0.f;
        for (int w = 0; w < 8; w++) s2 += red[w];
        red[0] = s2;
    }
    __syncthreads();
    float inv = 1.f / red[0];
    for (int n = tid; n < NCLS; n += 256)
        out[(size_t)b*NCLS + n] = lg[n]*inv;
}

// -------------------- launch ----------------------------------------------
extern "C" void kernel_launch(void* const* d_in, const int* in_sizes, int n_in,
                              void* d_out, int out_size)
{
    (void)in_sizes; (void)n_in; (void)out_size;
    const float* images = (const float*)d_in[0];
    const float* Wp     = (const float*)d_in[1];
    const float* bp     = (const float*)d_in[2];
    const float* cls    = (const float*)d_in[3];
    const float* pos    = (const float*)d_in[4];
    const float* ln1_g  = (const float*)d_in[5];
    const float* ln1_b  = (const float*)d_in[6];
    const float* Wq     = (const float*)d_in[7];
    const float* bq     = (const float*)d_in[8];
    const float* Wk     = (const float*)d_in[9];
    const float* bk     = (const float*)d_in[10];
    const float* Wv     = (const float*)d_in[11];
    const float* bv     = (const float*)d_in[12];
    const float* ln2_g  = (const float*)d_in[13];
    const float* ln2_b  = (const float*)d_in[14];
    const float* W1     = (const float*)d_in[15];
    const float* b1     = (const float*)d_in[16];
    const float* W2     = (const float*)d_in[17];
    const float* b2     = (const float*)d_in[18];
    const float* Wh     = (const float*)d_in[19];
    const float* bh     = (const float*)d_in[20];
    float* out = (float*)d_out;

    float *pX, *pQ, *pK, *pV;
    cudaGetSymbolAddress((void**)&pX, g_X);
    cudaGetSymbolAddress((void**)&pQ, g_Q);
    cudaGetSymbolAddress((void**)&pK, g_K);
    cudaGetSymbolAddress((void**)&pV, g_V);
    uint32_t *pAh, *pAl, *pHh, *pHl, *pUh, *pUl;
    cudaGetSymbolAddress((void**)&pAh, g_Ahw);
    cudaGetSymbolAddress((void**)&pAl, g_Alw);
    cudaGetSymbolAddress((void**)&pHh, g_Hhw);
    cudaGetSymbolAddress((void**)&pHl, g_Hlw);
    cudaGetSymbolAddress((void**)&pUh, g_Uhw);
    cudaGetSymbolAddress((void**)&pUl, g_Ulw);
    uint32_t *pWph,*pWpl,*pW1h,*pW1l,*pW2h,*pW2l,*pWqh,*pWql,*pWkh,*pWkl,*pWvh,*pWvl;
    cudaGetSymbolAddress((void**)&pWph, g_Wph);
    cudaGetSymbolAddress((void**)&pWpl, g_Wpl);
    cudaGetSymbolAddress((void**)&pW1h, g_W1h);
    cudaGetSymbolAddress((void**)&pW1l, g_W1l);
    cudaGetSymbolAddress((void**)&pW2h, g_W2h);
    cudaGetSymbolAddress((void**)&pW2l, g_W2l);
    cudaGetSymbolAddress((void**)&pWqh, g_Wqh);
    cudaGetSymbolAddress((void**)&pWql, g_Wql);
    cudaGetSymbolAddress((void**)&pWkh, g_Wkh);
    cudaGetSymbolAddress((void**)&pWkl, g_Wkl);
    cudaGetSymbolAddress((void**)&pWvh, g_Wvh);
    cudaGetSymbolAddress((void**)&pWvl, g_Wvl);

    cudaFuncSetAttribute(gemm16_kernel<0>,
        cudaFuncAttributeMaxDynamicSharedMemorySize, GEMM_SMEM);
    cudaFuncSetAttribute(gemm16_kernel<1>,
        cudaFuncAttributeMaxDynamicSharedMemorySize, GEMM_SMEM);
    cudaFuncSetAttribute(gemm16_kernel<2>,
        cudaFuncAttributeMaxDynamicSharedMemorySize, GEMM_SMEM);
    cudaFuncSetAttribute(qkv_kernel,
        cudaFuncAttributeMaxDynamicSharedMemorySize, GEMM_SMEM);
    cudaFuncSetAttribute(attn_kernel,
        cudaFuncAttributeMaxDynamicSharedMemorySize, ATTN_SMEM_BYTES);

    // ---- pre-split all weights into fp16 hi/lo (once per launch) ----
    presplit_b<<<dim3((DIM+255)/256,  DIM/2),        256>>>(Wp, pWph, pWpl, DIM);
    presplit_b<<<dim3((MLPD+255)/256, NL*DIM/2),     256>>>(W1, pW1h, pW1l, MLPD);
    presplit_b<<<dim3((DIM+255)/256,  NL*MLPD/2),    256>>>(W2, pW2h, pW2l, DIM);
    presplit_b<<<dim3(1, NL*NHD*HD/2), 64>>>(Wq, pWqh, pWql, HD);
    presplit_b<<<dim3(1, NL*NHD*HD/2), 64>>>(Wk, pWkh, pWkl, HD);
    presplit_b<<<dim3(1, NL*NHD*HD/2), 64>>>(Wv, pWvh, pWvl, HD);

    // ---- patch embed: (6272 x 768) @ (768 x 768) -> f32 in g_Q ----
    patchify_kernel<<<(BB*NPAT*DIM + 255)/256, 256>>>(images);
    gemm16_kernel<0><<<dim3(DIM/64, (BB*NPAT+127)/128), 256, GEMM_SMEM>>>(
        (const __half*)pAh, (const __half*)pAl, DIM,
        pWph, pWpl, DIM, bp, pQ, 0, 0, DIM, BB*NPAT, DIM);
    assemble_kernel<<<(NTOK*DIM + 255)/256, 256>>>(cls, pos);

    for (int l = 0; l < NL; l++) {
        ln_kernel<<<NTOK, 256>>>(pX, ln1_g + l*DIM, ln1_b + l*DIM);
        qkv_kernel<<<dim3(1, MT128, NHD*3), 256, GEMM_SMEM>>>(bq, bk, bv, l);
        attn_kernel<<<BB*NHD, 128, ATTN_SMEM_BYTES>>>(pQ, pK, pV, pX);
        ln_kernel<<<NTOK, 256>>>(pX, ln2_g + l*DIM, ln2_b + l*DIM);
        gemm16_kernel<1><<<dim3(MLPD/64, MT128), 256, GEMM_SMEM>>>(
            (const __half*)pHh, (const __half*)pHl, DIM,
            pW1h + (size_t)l*(DIM/2)*MLPD, pW1l + (size_t)l*(DIM/2)*MLPD, MLPD,
            b1 + (size_t)l*MLPD, 0, pUh, pUl, MLPD, NTOK, DIM);
        gemm16_kernel<2><<<dim3(DIM/64, MT128), 256, GEMM_SMEM>>>(
            (const __half*)pUh, (const __half*)pUl, MLPD,
            pW2h + (size_t)l*(MLPD/2)*DIM, pW2l + (size_t)l*(MLPD/2)*DIM, DIM,
            b2 + (size_t)l*DIM, pX, 0, 0, DIM, NTOK, MLPD);
    }

    head_kernel<<<BB, 256>>>(pX, Wh, bh, out);
}

// round 16
// speedup vs baseline: 1.1295x; 1.1295x over previous
#include <cuda_runtime.h>
#include <cuda_fp16.h>
#include <math.h>
#include <stdint.h>

#define BB   32
#define SEQ  197
#define DIM  768
#define NHD  12
#define HD   64
#define NL   12
#define NCLS 1000
#define MLPD 3072
#define NTOK (BB*SEQ)     // 6304
#define NPAT 196
#define MT128 ((NTOK+127)/128)   // 50 M-tiles of 128

// -------------------- scratch (device globals; no allocation allowed) -----
__device__ float g_X[NTOK*DIM];
__device__ float g_H[NTOK*DIM];
__device__ float g_A[BB*NPAT*DIM];
__device__ float g_Q[NTOK*DIM];
__device__ float g_K[NTOK*DIM];
__device__ float g_V[NTOK*DIM];
__device__ float g_U[(size_t)NTOK*MLPD];

// -------------------- helpers ---------------------------------------------
__device__ __forceinline__ void split2(float x, float y, uint32_t& hw, uint32_t& lw)
{
    __half2 h = __floats2half2_rn(x, y);
    float2 hf = __half22float2(h);
    __half2 l = __floats2half2_rn(x - hf.x, y - hf.y);
    hw = *(uint32_t*)&h;
    lw = *(uint32_t*)&l;
}

__device__ __forceinline__ void mma_f16(float* cc, const uint32_t* a, const uint32_t* b)
{
    asm volatile(
        "mma.sync.aligned.m16n8k16.row.col.f32.f16.f16.f32 "
        "{%0,%1,%2,%3}, {%4,%5,%6,%7}, {%8,%9}, {%0,%1,%2,%3};\n"
        : "+f"(cc[0]), "+f"(cc[1]), "+f"(cc[2]), "+f"(cc[3])
        : "r"(a[0]), "r"(a[1]), "r"(a[2]), "r"(a[3]),
          "r"(b[0]), "r"(b[1]));
}

// -------------------- patchify: (B,C,224,224) -> (B*196, 768) -------------
__global__ void patchify_kernel(const float* __restrict__ img)
{
    int idx = blockIdx.x*256 + threadIdx.x;
    const int total = BB*NPAT*DIM;
    if (idx >= total) return;
    int f = idx % DIM;
    int p = (idx / DIM) % NPAT;
    int b = idx / (DIM*NPAT);
    int c = f >> 8;
    int rem = f & 255;
    int i = rem >> 4;
    int j = rem & 15;
    int pr = p / 14, pc = p % 14;
    g_A[idx] = img[(((size_t)b*3 + c)*224 + (pr*16+i))*224 + (pc*16+j)];
}

// -------------------- assemble tokens: cls + embed + pos -> X -------------
__global__ void assemble_kernel(const float* __restrict__ cls,
                                const float* __restrict__ pos)
{
    int idx = blockIdx.x*256 + threadIdx.x;
    if (idx >= NTOK*DIM) return;
    int d = idx % DIM;
    int s = (idx / DIM) % SEQ;
    int b = idx / (DIM*SEQ);
    float v = (s == 0) ? cls[d] : g_H[((size_t)b*NPAT + (s-1))*DIM + d];
    g_X[idx] = v + pos[s*DIM + d];
}

// ==================== FP16x3 GEMM, 128x128 block tile =====================
// 256 threads, 8 warps in 2(M) x 4(N); warp tile 64x32; BK=32.
// f32 -> fp16 hi/lo split ONCE at smem store. Double-buffered, 1 barrier/iter.
// LDS per MMA = 1.0 (vs 1.33 for the 64-wide tile).
// EPI 0: C = acc + bias ; 1: C = gelu(acc+bias) ; 2: C += acc + bias

#define AWS 20                  // A row stride (words)
#define BWS 136                 // B kpair-row stride (words); 136 % 32 == 8
#define A_ST (128*AWS)          // 2560 words per stage per (hi|lo)
#define B_ST (16*BWS)           // 2176 words per stage per (hi|lo)
#define OFF_AH 0
#define OFF_AL (2*A_ST)
#define OFF_BH (4*A_ST)
#define OFF_BL (4*A_ST + 2*B_ST)
#define G128_WORDS (4*A_ST + 4*B_ST)   // 18944
#define G128_SMEM (G128_WORDS*4)       // 75776 bytes

template<int EPI>
__global__ __launch_bounds__(256) void gemm128_kernel(
    const float* __restrict__ A, int lda,
    const float* __restrict__ Bm, int ldb,
    const float* __restrict__ bias,
    float* __restrict__ C, int ldc, int M, int K)
{
    extern __shared__ uint32_t smw[];
    int m0 = blockIdx.y*128, n0 = blockIdx.x*128;

    int tid  = threadIdx.x;
    int lane = tid & 31, wid = tid >> 5;
    int warpM = wid >> 2, warpN = wid & 3;
    int g = lane >> 2, c = lane & 3;

    int arow = tid >> 3, ac4 = tid & 7;     // A: rows arow+32i, cols ac4*4..+3
    int bkp  = tid >> 4, bn4 = tid & 15;    // B: kpair bkp, col slots bn4*4 (+64)

    float acc[4][4][4] = {};
    float4 ra[4], rb[2][2];

    // ---- prologue: LDG chunk 0 ----
#pragma unroll
    for (int i = 0; i < 4; i++) {
        int gm = m0 + arow + i*32;
        ra[i] = (gm < M) ? *(const float4*)&A[(size_t)gm*lda + ac4*4]
                         : make_float4(0.f,0.f,0.f,0.f);
    }
#pragma unroll
    for (int ni = 0; ni < 2; ni++) {
        int col = n0 + ni*64 + bn4*4;
        rb[ni][0] = *(const float4*)&Bm[(size_t)(2*bkp  )*ldb + col];
        rb[ni][1] = *(const float4*)&Bm[(size_t)(2*bkp+1)*ldb + col];
    }

    int p = 0;
    for (int k0 = 0; k0 < K; k0 += 32) {
        uint32_t* AH = smw + OFF_AH + p*A_ST;
        uint32_t* AL = smw + OFF_AL + p*A_ST;
        uint32_t* BH = smw + OFF_BH + p*B_ST;
        uint32_t* BL = smw + OFF_BL + p*B_ST;

        // ---- split+store A ----
#pragma unroll
        for (int i = 0; i < 4; i++) {
            int row = arow + i*32;
            uint32_t h0,h1,l0,l1;
            split2(ra[i].x, ra[i].y, h0, l0);
            split2(ra[i].z, ra[i].w, h1, l1);
            *(uint2*)&AH[row*AWS + ac4*2] = make_uint2(h0, h1);
            *(uint2*)&AL[row*AWS + ac4*2] = make_uint2(l0, l1);
        }
        // ---- split+store B (pair k rows into half2 words) ----
#pragma unroll
        for (int ni = 0; ni < 2; ni++) {
            float r0[4] = {rb[ni][0].x, rb[ni][0].y, rb[ni][0].z, rb[ni][0].w};
            float r1[4] = {rb[ni][1].x, rb[ni][1].y, rb[ni][1].z, rb[ni][1].w};
            uint32_t hw[4], lw[4];
#pragma unroll
            for (int j = 0; j < 4; j++)
                split2(r0[j], r1[j], hw[j], lw[j]);
            int col = ni*64 + bn4*4;
            *(uint4*)&BH[bkp*BWS + col] = make_uint4(hw[0],hw[1],hw[2],hw[3]);
            *(uint4*)&BL[bkp*BWS + col] = make_uint4(lw[0],lw[1],lw[2],lw[3]);
        }
        __syncthreads();

        // ---- prefetch next chunk ----
        if (k0 + 32 < K) {
            int kn = k0 + 32;
#pragma unroll
            for (int i = 0; i < 4; i++) {
                int gm = m0 + arow + i*32;
                ra[i] = (gm < M) ? *(const float4*)&A[(size_t)gm*lda + kn + ac4*4]
                                 : make_float4(0.f,0.f,0.f,0.f);
            }
#pragma unroll
            for (int ni = 0; ni < 2; ni++) {
                int col = n0 + ni*64 + bn4*4;
                rb[ni][0] = *(const float4*)&Bm[(size_t)(kn + 2*bkp  )*ldb + col];
                rb[ni][1] = *(const float4*)&Bm[(size_t)(kn + 2*bkp+1)*ldb + col];
            }
        }

        // ---- compute: 2 k16 steps ----
#pragma unroll
        for (int kk = 0; kk < 2; kk++) {
            int ko = kk*8;
            uint32_t ah[4][4], al[4][4];
#pragma unroll
            for (int mt = 0; mt < 4; mt++) {
                int r = warpM*64 + mt*16 + g;
                ah[mt][0] = AH[ r   *AWS + ko + c];
                ah[mt][1] = AH[(r+8)*AWS + ko + c];
                ah[mt][2] = AH[ r   *AWS + ko + c + 4];
                ah[mt][3] = AH[(r+8)*AWS + ko + c + 4];
                al[mt][0] = AL[ r   *AWS + ko + c];
                al[mt][1] = AL[(r+8)*AWS + ko + c];
                al[mt][2] = AL[ r   *AWS + ko + c + 4];
                al[mt][3] = AL[(r+8)*AWS + ko + c + 4];
            }
#pragma unroll
            for (int nt = 0; nt < 4; nt++) {
                int ncol = warpN*32 + nt*8 + g;
                uint32_t bh[2], bl[2];
                bh[0] = BH[(ko + c    )*BWS + ncol];
                bh[1] = BH[(ko + c + 4)*BWS + ncol];
                bl[0] = BL[(ko + c    )*BWS + ncol];
                bl[1] = BL[(ko + c + 4)*BWS + ncol];
#pragma unroll
                for (int mt = 0; mt < 4; mt++) {
                    mma_f16(acc[mt][nt], ah[mt], bl);
                    mma_f16(acc[mt][nt], al[mt], bh);
                    mma_f16(acc[mt][nt], ah[mt], bh);
                }
            }
        }
        p ^= 1;
    }

    // ---- epilogue ----
#pragma unroll
    for (int mt = 0; mt < 4; mt++) {
#pragma unroll
        for (int nt = 0; nt < 4; nt++) {
            int r0  = m0 + warpM*64 + mt*16 + g;
            int col = n0 + warpN*32 + nt*8 + 2*c;
#pragma unroll
            for (int half = 0; half < 2; half++) {
                int gm = r0 + half*8;
                if (gm >= M) continue;
#pragma unroll
                for (int jj = 0; jj < 2; jj++) {
                    int gn = col + jj;
                    float v = acc[mt][nt][half*2 + jj] + bias[gn];
                    float* cp = &C[(size_t)gm*ldc + gn];
                    if (EPI == 1) v = 0.5f*v*(1.f + erff(v*0.70710678118654752f));
                    if (EPI == 2) v += *cp;
                    *cp = v;
                }
            }
        }
    }
}

// ==================== FP16x3 GEMM, 128x64 tile (QKV) ======================
#define QAWS 20
#define QBWS 72
#define QA_ST (128*QAWS)
#define QB_ST (16*QBWS)
#define QOFF_AH 0
#define QOFF_AL (2*QA_ST)
#define QOFF_BH (4*QA_ST)
#define QOFF_BL (4*QA_ST + 2*QB_ST)
#define QGEMM_WORDS (4*QA_ST + 4*QB_ST)
#define QGEMM_SMEM (QGEMM_WORDS*4)   // 59392

__device__ __forceinline__ void gemm64_tile(
    const float* __restrict__ A, int lda,
    const float* __restrict__ Bm, int ldb,
    const float* __restrict__ bias,
    float* __restrict__ C, int ldc,
    int M, int K, int m0, int n0)
{
    extern __shared__ uint32_t smw[];

    int tid  = threadIdx.x;
    int lane = tid & 31, wid = tid >> 5;
    int warpM = wid >> 1, warpN = wid & 1;
    int g = lane >> 2, c = lane & 3;

    int arow = tid >> 3, ac4 = tid & 7;
    int bp   = tid >> 4, bc4 = tid & 15;

    float acc[2][4][4] = {};
    float4 ra[4], rb0, rb1;

#pragma unroll
    for (int i = 0; i < 4; i++) {
        int gm = m0 + arow + i*32;
        ra[i] = (gm < M) ? *(const float4*)&A[(size_t)gm*lda + ac4*4]
                         : make_float4(0.f,0.f,0.f,0.f);
    }
    rb0 = *(const float4*)&Bm[(size_t)(2*bp  )*ldb + n0 + bc4*4];
    rb1 = *(const float4*)&Bm[(size_t)(2*bp+1)*ldb + n0 + bc4*4];

    int p = 0;
    for (int k0 = 0; k0 < K; k0 += 32) {
        uint32_t* AH = smw + QOFF_AH + p*QA_ST;
        uint32_t* AL = smw + QOFF_AL + p*QA_ST;
        uint32_t* BH = smw + QOFF_BH + p*QB_ST;
        uint32_t* BL = smw + QOFF_BL + p*QB_ST;
#pragma unroll
        for (int i = 0; i < 4; i++) {
            int row = arow + i*32;
            uint32_t h0,h1,l0,l1;
            split2(ra[i].x, ra[i].y, h0, l0);
            split2(ra[i].z, ra[i].w, h1, l1);
            *(uint2*)&AH[row*QAWS + ac4*2] = make_uint2(h0, h1);
            *(uint2*)&AL[row*QAWS + ac4*2] = make_uint2(l0, l1);
        }
        {
            float r0[4] = {rb0.x, rb0.y, rb0.z, rb0.w};
            float r1[4] = {rb1.x, rb1.y, rb1.z, rb1.w};
            uint32_t hw[4], lw[4];
#pragma unroll
            for (int j = 0; j < 4; j++)
                split2(r0[j], r1[j], hw[j], lw[j]);
            *(uint4*)&BH[bp*QBWS + bc4*4] = make_uint4(hw[0],hw[1],hw[2],hw[3]);
            *(uint4*)&BL[bp*QBWS + bc4*4] = make_uint4(lw[0],lw[1],lw[2],lw[3]);
        }
        __syncthreads();

        if (k0 + 32 < K) {
            int kn = k0 + 32;
#pragma unroll
            for (int i = 0; i < 4; i++) {
                int gm = m0 + arow + i*32;
                ra[i] = (gm < M) ? *(const float4*)&A[(size_t)gm*lda + kn + ac4*4]
                                 : make_float4(0.f,0.f,0.f,0.f);
            }
            rb0 = *(const float4*)&Bm[(size_t)(kn + 2*bp  )*ldb + n0 + bc4*4];
            rb1 = *(const float4*)&Bm[(size_t)(kn + 2*bp+1)*ldb + n0 + bc4*4];
        }

#pragma unroll
        for (int kk = 0; kk < 2; kk++) {
            int ko = kk*8;
            uint32_t ah[2][4], al[2][4];
#pragma unroll
            for (int mt = 0; mt < 2; mt++) {
                int r = warpM*32 + mt*16 + g;
                ah[mt][0] = AH[ r   *QAWS + ko + c];
                ah[mt][1] = AH[(r+8)*QAWS + ko + c];
                ah[mt][2] = AH[ r   *QAWS + ko + c + 4];
                ah[mt][3] = AH[(r+8)*QAWS + ko + c + 4];
                al[mt][0] = AL[ r   *QAWS + ko + c];
                al[mt][1] = AL[(r+8)*QAWS + ko + c];
                al[mt][2] = AL[ r   *QAWS + ko + c + 4];
                al[mt][3] = AL[(r+8)*QAWS + ko + c + 4];
            }
            uint32_t bh[4][2], bl[4][2];
#pragma unroll
            for (int nt = 0; nt < 4; nt++) {
                int ncol = warpN*32 + nt*8 + g;
                bh[nt][0] = BH[(ko + c    )*QBWS + ncol];
                bh[nt][1] = BH[(ko + c + 4)*QBWS + ncol];
                bl[nt][0] = BL[(ko + c    )*QBWS + ncol];
                bl[nt][1] = BL[(ko + c + 4)*QBWS + ncol];
            }
#pragma unroll
            for (int mt = 0; mt < 2; mt++)
#pragma unroll
                for (int nt = 0; nt < 4; nt++) {
                    mma_f16(acc[mt][nt], ah[mt], bl[nt]);
                    mma_f16(acc[mt][nt], al[mt], bh[nt]);
                    mma_f16(acc[mt][nt], ah[mt], bh[nt]);
                }
        }
        p ^= 1;
    }

#pragma unroll
    for (int mt = 0; mt < 2; mt++) {
#pragma unroll
        for (int nt = 0; nt < 4; nt++) {
            int r0  = m0 + warpM*32 + mt*16 + g;
            int col = n0 + warpN*32 + nt*8 + 2*c;
#pragma unroll
            for (int half = 0; half < 2; half++) {
                int gm = r0 + half*8;
                if (gm >= M) continue;
#pragma unroll
                for (int jj = 0; jj < 2; jj++) {
                    int gn = col + jj;
                    float v = acc[mt][nt][half*2 + jj] + bias[gn];
                    C[(size_t)gm*ldc + gn] = v;
                }
            }
        }
    }
}

// per-head QKV. grid: (1, Mtiles128, 36 = 12 heads x 3)
__global__ __launch_bounds__(256) void qkv_mma_kernel(
    const float* __restrict__ Wq, const float* __restrict__ bq,
    const float* __restrict__ Wk, const float* __restrict__ bk,
    const float* __restrict__ Wv, const float* __restrict__ bv,
    int layer)
{
    int z = blockIdx.z;
    int h = z % NHD, t = z / NHD;
    const float* W; const float* bi; float* C;
    if (t == 0)      { W = Wq; bi = bq; C = g_Q; }
    else if (t == 1) { W = Wk; bi = bk; C = g_K; }
    else             { W = Wv; bi = bv; C = g_V; }
    size_t off = (size_t)layer*NHD + h;
    gemm64_tile(g_H + h*HD, DIM,
                W + off*HD*HD, HD,
                bi + off*HD,
                C + h*HD, DIM,
                NTOK, HD, blockIdx.y*128, 0);
}

// -------------------- layernorm ------------------------------------------
__global__ __launch_bounds__(256) void ln_kernel(
    const float* __restrict__ X, float* __restrict__ H,
    const float* __restrict__ gw, const float* __restrict__ bw)
{
    __shared__ float rs[8], rq[8];
    int row = blockIdx.x, tid = threadIdx.x;
    int lane = tid & 31, wid = tid >> 5;
    const float* x = X + (size_t)row*DIM;
    float v0 = x[tid], v1 = x[tid+256], v2 = x[tid+512];
    float s = v0+v1+v2;
    float q = v0*v0 + v1*v1 + v2*v2;
#pragma unroll
    for (int o = 16; o; o >>= 1) {
        s += __shfl_xor_sync(0xffffffffu, s, o);
        q += __shfl_xor_sync(0xffffffffu, q, o);
    }
    if (lane == 0) { rs[wid] = s; rq[wid] = q; }
    __syncthreads();
    if (tid == 0) {
        float ts = 0.f, tq = 0.f;
        for (int w = 0; w < 8; w++) { ts += rs[w]; tq += rq[w]; }
        rs[0] = ts; rq[0] = tq;
    }
    __syncthreads();
    float mean = rs[0]*(1.0f/DIM);
    float var  = rq[0]*(1.0f/DIM) - mean*mean;
    float inv  = rsqrtf(var + 1e-5f);
    float* hrow = H + (size_t)row*DIM;
    hrow[tid]     = (v0-mean)*inv*gw[tid]     + bw[tid];
    hrow[tid+256] = (v1-mean)*inv*gw[tid+256] + bw[tid+256];
    hrow[tid+512] = (v2-mean)*inv*gw[tid+512] + bw[tid+512];
}

// -------------------- attention: warp-parallel queries -------------------
#define PSTR 208
#define ATTN_SMEM_FLOATS (2*SEQ*HD + 4*HD + 4*PSTR)
#define ATTN_SMEM_BYTES  (ATTN_SMEM_FLOATS*4)

__global__ __launch_bounds__(128) void attn_kernel(
    const float* __restrict__ Q, const float* __restrict__ K,
    const float* __restrict__ V, float* __restrict__ X)
{
    extern __shared__ float sm[];
    float* Ks = sm;
    float* Vs = Ks + SEQ*HD;
    float* qs = Vs + SEQ*HD;
    float* ps = qs + 4*HD;

    int bh = blockIdx.x;
    int b = bh / NHD, h = bh % NHD;
    int tid = threadIdx.x;
    int lane = tid & 31, wid = tid >> 5;
    size_t base = (size_t)b*SEQ*DIM + (size_t)h*HD;

    for (int idx = tid; idx < SEQ*32; idx += 128) {
        int t = idx >> 5, e2 = idx & 31;
        ((float2*)Ks)[idx] = *(const float2*)&K[base + (size_t)t*DIM + 2*e2];
        ((float2*)Vs)[idx] = *(const float2*)&V[base + (size_t)t*DIM + 2*e2];
    }
    __syncthreads();

    float* myq = qs + wid*HD;
    float* myp = ps + wid*PSTR;
    const float2* q2 = (const float2*)myq;
    const float2* vr = (const float2*)Vs;

    for (int s = wid; s < SEQ; s += 4) {
        *(float2*)&myq[2*lane] = *(const float2*)&Q[base + (size_t)s*DIM + 2*lane];
        __syncwarp();

        float lm = -1e30f;
        for (int j = lane; j < SEQ; j += 32) {
            const float2* kr = (const float2*)&Ks[j*HD];
            float d = 0.f;
#pragma unroll
            for (int e2 = 0; e2 < 32; e2++) {
                int ee = (e2 + lane) & 31;
                float2 kv = kr[ee];
                float2 qv = q2[ee];
                d = fmaf(qv.x, kv.x, d);
                d = fmaf(qv.y, kv.y, d);
            }
            d *= 0.125f;
            myp[j] = d;
            lm = fmaxf(lm, d);
        }
#pragma unroll
        for (int o = 16; o; o >>= 1)
            lm = fmaxf(lm, __shfl_xor_sync(0xffffffffu, lm, o));

        float ls = 0.f;
        for (int j = lane; j < SEQ; j += 32) {
            float e = expf(myp[j] - lm);
            myp[j] = e;
            ls += e;
        }
#pragma unroll
        for (int o = 16; o; o >>= 1)
            ls += __shfl_xor_sync(0xffffffffu, ls, o);
        float inv = 1.f / ls;
        __syncwarp();

        float2 acc = make_float2(0.f, 0.f);
        int t = 0;
        for (; t + 4 <= SEQ; t += 4) {
#pragma unroll
            for (int u = 0; u < 4; u++) {
                float p = myp[t+u];
                float2 vv = vr[(t+u)*32 + lane];
                acc.x = fmaf(p, vv.x, acc.x);
                acc.y = fmaf(p, vv.y, acc.y);
            }
        }
        for (; t < SEQ; t++) {
            float p = myp[t];
            float2 vv = vr[t*32 + lane];
            acc.x = fmaf(p, vv.x, acc.x);
            acc.y = fmaf(p, vv.y, acc.y);
        }

        float* xp = &X[base + (size_t)s*DIM + 2*lane];
        float2 xo = *(float2*)xp;
        xo.x += acc.x * inv;
        xo.y += acc.y * inv;
        *(float2*)xp = xo;
        __syncwarp();
    }
}

// -------------------- classifier head + softmax --------------------------
__global__ __launch_bounds__(256) void head_kernel(
    const float* __restrict__ X, const float* __restrict__ Wh,
    const float* __restrict__ bh, float* __restrict__ out)
{
    __shared__ float xr[DIM];
    __shared__ float lg[NCLS];
    __shared__ float red[8];
    int b = blockIdx.x, tid = threadIdx.x;
    int lane = tid & 31, wid = tid >> 5;

    for (int d = tid; d < DIM; d += 256) xr[d] = X[(size_t)b*SEQ*DIM + d];
    __syncthreads();

    for (int n = tid; n < NCLS; n += 256) {
        float a = bh[n];
        for (int k = 0; k < DIM; k++)
            a = fmaf(xr[k], Wh[(size_t)k*NCLS + n], a);
        lg[n] = a;
    }
    __syncthreads();

    float lm = -1e30f;
    for (int n = tid; n < NCLS; n += 256) lm = fmaxf(lm, lg[n]);
#pragma unroll
    for (int o = 16; o; o >>= 1) lm = fmaxf(lm, __shfl_xor_sync(0xffffffffu, lm, o));
    if (lane == 0) red[wid] = lm;
    __syncthreads();
    if (tid == 0) {
        float m = red[0];
        for (int w = 1; w < 8; w++) m = fmaxf(m, red[w]);
        red[0] = m;
    }
    __syncthreads();
    float mx = red[0];

    float ls = 0.f;
    for (int n = tid; n < NCLS; n += 256) {
        float e = expf(lg[n] - mx);
        lg[n] = e;
        ls += e;
    }
#pragma unroll
    for (int o = 16; o; o >>= 1) ls += __shfl_xor_sync(0xffffffffu, ls, o);
    __syncthreads();
    if (lane == 0) red[wid] = ls;
    __syncthreads();
    if (tid == 0) {
        float s2 = 0.f;
        for (int w = 0; w < 8; w++) s2 += red[w];
        red[0] = s2;
    }
    __syncthreads();
    float inv = 1.f / red[0];
    for (int n = tid; n < NCLS; n += 256)
        out[(size_t)b*NCLS + n] = lg[n]*inv;
}

// -------------------- launch ---------------------------------------------
extern "C" void kernel_launch(void* const* d_in, const int* in_sizes, int n_in,
                              void* d_out, int out_size)
{
    (void)in_sizes; (void)n_in; (void)out_size;
    const float* images = (const float*)d_in[0];
    const float* Wp     = (const float*)d_in[1];
    const float* bp     = (const float*)d_in[2];
    const float* cls    = (const float*)d_in[3];
    const float* pos    = (const float*)d_in[4];
    const float* ln1_g  = (const float*)d_in[5];
    const float* ln1_b  = (const float*)d_in[6];
    const float* Wq     = (const float*)d_in[7];
    const float* bq     = (const float*)d_in[8];
    const float* Wk     = (const float*)d_in[9];
    const float* bk     = (const float*)d_in[10];
    const float* Wv     = (const float*)d_in[11];
    const float* bv     = (const float*)d_in[12];
    const float* ln2_g  = (const float*)d_in[13];
    const float* ln2_b  = (const float*)d_in[14];
    const float* W1     = (const float*)d_in[15];
    const float* b1     = (const float*)d_in[16];
    const float* W2     = (const float*)d_in[17];
    const float* b2     = (const float*)d_in[18];
    const float* Wh     = (const float*)d_in[19];
    const float* bh     = (const float*)d_in[20];
    float* out = (float*)d_out;

    float *pA, *pH, *pX, *pQ, *pK, *pV, *pU;
    cudaGetSymbolAddress((void**)&pA, g_A);
    cudaGetSymbolAddress((void**)&pH, g_H);
    cudaGetSymbolAddress((void**)&pX, g_X);
    cudaGetSymbolAddress((void**)&pQ, g_Q);
    cudaGetSymbolAddress((void**)&pK, g_K);
    cudaGetSymbolAddress((void**)&pV, g_V);
    cudaGetSymbolAddress((void**)&pU, g_U);

    cudaFuncSetAttribute(gemm128_kernel<0>,
        cudaFuncAttributeMaxDynamicSharedMemorySize, G128_SMEM);
    cudaFuncSetAttribute(gemm128_kernel<1>,
        cudaFuncAttributeMaxDynamicSharedMemorySize, G128_SMEM);
    cudaFuncSetAttribute(gemm128_kernel<2>,
        cudaFuncAttributeMaxDynamicSharedMemorySize, G128_SMEM);
    cudaFuncSetAttribute(qkv_mma_kernel,
        cudaFuncAttributeMaxDynamicSharedMemorySize, QGEMM_SMEM);
    cudaFuncSetAttribute(attn_kernel,
        cudaFuncAttributeMaxDynamicSharedMemorySize, ATTN_SMEM_BYTES);

    // Patch embed: (6272 x 768) @ (768 x 768)
    patchify_kernel<<<(BB*NPAT*DIM + 255)/256, 256>>>(images);
    gemm128_kernel<0><<<dim3(DIM/128, (BB*NPAT+127)/128), 256, G128_SMEM>>>(
        pA, DIM, Wp, DIM, bp, pH, DIM, BB*NPAT, DIM);
    assemble_kernel<<<(NTOK*DIM + 255)/256, 256>>>(cls, pos);

    for (int l = 0; l < NL; l++) {
        ln_kernel<<<NTOK, 256>>>(pX, pH, ln1_g + l*DIM, ln1_b + l*DIM);
        qkv_mma_kernel<<<dim3(1, MT128, NHD*3), 256, QGEMM_SMEM>>>(
            Wq, bq, Wk, bk, Wv, bv, l);
        attn_kernel<<<BB*NHD, 128, ATTN_SMEM_BYTES>>>(pQ, pK, pV, pX);
        ln_kernel<<<NTOK, 256>>>(pX, pH, ln2_g + l*DIM, ln2_b + l*DIM);
        gemm128_kernel<1><<<dim3(MLPD/128, MT128), 256, G128_SMEM>>>(
            pH, DIM, W1 + (size_t)l*DIM*MLPD, MLPD, b1 + (size_t)l*MLPD,
            pU, MLPD, NTOK, DIM);
        gemm128_kernel<2><<<dim3(DIM/128, MT128), 256, G128_SMEM>>>(
            pU, MLPD, W2 + (size_t)l*MLPD*DIM, DIM, b2 + (size_t)l*DIM,
            pX, DIM, NTOK, MLPD);
    }

    head_kernel<<<BB, 256>>>(pX, Wh, bh, out);
}

// round 17
// speedup vs baseline: 1.5870x; 1.4051x over previous
#include <cuda_runtime.h>
#include <cuda_fp16.h>
#include <math.h>
#include <stdint.h>

#define BB   32
#define SEQ  197
#define DIM  768
#define NHD  12
#define HD   64
#define NL   12
#define NCLS 1000
#define MLPD 3072
#define NTOK (BB*SEQ)     // 6304
#define NPAT 196
#define MT128 ((NTOK+127)/128)   // 50 M-tiles of 128

// -------------------- scratch (device globals; no allocation allowed) -----
__device__ float g_X[NTOK*DIM];
__device__ float g_H[NTOK*DIM];
__device__ float g_A[BB*NPAT*DIM];
__device__ float g_Q[NTOK*DIM];
__device__ float g_K[NTOK*DIM];
__device__ float g_V[NTOK*DIM];
__device__ float g_U[(size_t)NTOK*MLPD];

// -------------------- helpers ---------------------------------------------
__device__ __forceinline__ void split2(float x, float y, uint32_t& hw, uint32_t& lw)
{
    __half2 h = __floats2half2_rn(x, y);
    float2 hf = __half22float2(h);
    __half2 l = __floats2half2_rn(x - hf.x, y - hf.y);
    hw = *(uint32_t*)&h;
    lw = *(uint32_t*)&l;
}

__device__ __forceinline__ void mma_f16(float* cc, const uint32_t* a, const uint32_t* b)
{
    asm volatile(
        "mma.sync.aligned.m16n8k16.row.col.f32.f16.f16.f32 "
        "{%0,%1,%2,%3}, {%4,%5,%6,%7}, {%8,%9}, {%0,%1,%2,%3};\n"
        : "+f"(cc[0]), "+f"(cc[1]), "+f"(cc[2]), "+f"(cc[3])
        : "r"(a[0]), "r"(a[1]), "r"(a[2]), "r"(a[3]),
          "r"(b[0]), "r"(b[1]));
}

// -------------------- patchify: (B,C,224,224) -> (B*196, 768) -------------
__global__ void patchify_kernel(const float* __restrict__ img)
{
    int idx = blockIdx.x*256 + threadIdx.x;
    const int total = BB*NPAT*DIM;
    if (idx >= total) return;
    int f = idx % DIM;
    int p = (idx / DIM) % NPAT;
    int b = idx / (DIM*NPAT);
    int c = f >> 8;
    int rem = f & 255;
    int i = rem >> 4;
    int j = rem & 15;
    int pr = p / 14, pc = p % 14;
    g_A[idx] = img[(((size_t)b*3 + c)*224 + (pr*16+i))*224 + (pc*16+j)];
}

// -------------------- assemble tokens: cls + embed + pos -> X -------------
__global__ void assemble_kernel(const float* __restrict__ cls,
                                const float* __restrict__ pos)
{
    int idx = blockIdx.x*256 + threadIdx.x;
    if (idx >= NTOK*DIM) return;
    int d = idx % DIM;
    int s = (idx / DIM) % SEQ;
    int b = idx / (DIM*SEQ);
    float v = (s == 0) ? cls[d] : g_H[((size_t)b*NPAT + (s-1))*DIM + d];
    g_X[idx] = v + pos[s*DIM + d];
}

// ==================== FP16x3 GEMM, 128x128 block tile =====================
#define AWS 20
#define BWS 136
#define A_ST (128*AWS)
#define B_ST (16*BWS)
#define OFF_AH 0
#define OFF_AL (2*A_ST)
#define OFF_BH (4*A_ST)
#define OFF_BL (4*A_ST + 2*B_ST)
#define G128_WORDS (4*A_ST + 4*B_ST)
#define G128_SMEM (G128_WORDS*4)

template<int EPI>
__global__ __launch_bounds__(256) void gemm128_kernel(
    const float* __restrict__ A, int lda,
    const float* __restrict__ Bm, int ldb,
    const float* __restrict__ bias,
    float* __restrict__ C, int ldc, int M, int K)
{
    extern __shared__ uint32_t smw[];
    int m0 = blockIdx.y*128, n0 = blockIdx.x*128;

    int tid  = threadIdx.x;
    int lane = tid & 31, wid = tid >> 5;
    int warpM = wid >> 2, warpN = wid & 3;
    int g = lane >> 2, c = lane & 3;

    int arow = tid >> 3, ac4 = tid & 7;
    int bkp  = tid >> 4, bn4 = tid & 15;

    float acc[4][4][4] = {};
    float4 ra[4], rb[2][2];

#pragma unroll
    for (int i = 0; i < 4; i++) {
        int gm = m0 + arow + i*32;
        ra[i] = (gm < M) ? *(const float4*)&A[(size_t)gm*lda + ac4*4]
                         : make_float4(0.f,0.f,0.f,0.f);
    }
#pragma unroll
    for (int ni = 0; ni < 2; ni++) {
        int col = n0 + ni*64 + bn4*4;
        rb[ni][0] = *(const float4*)&Bm[(size_t)(2*bkp  )*ldb + col];
        rb[ni][1] = *(const float4*)&Bm[(size_t)(2*bkp+1)*ldb + col];
    }

    int p = 0;
    for (int k0 = 0; k0 < K; k0 += 32) {
        uint32_t* AH = smw + OFF_AH + p*A_ST;
        uint32_t* AL = smw + OFF_AL + p*A_ST;
        uint32_t* BH = smw + OFF_BH + p*B_ST;
        uint32_t* BL = smw + OFF_BL + p*B_ST;

#pragma unroll
        for (int i = 0; i < 4; i++) {
            int row = arow + i*32;
            uint32_t h0,h1,l0,l1;
            split2(ra[i].x, ra[i].y, h0, l0);
            split2(ra[i].z, ra[i].w, h1, l1);
            *(uint2*)&AH[row*AWS + ac4*2] = make_uint2(h0, h1);
            *(uint2*)&AL[row*AWS + ac4*2] = make_uint2(l0, l1);
        }
#pragma unroll
        for (int ni = 0; ni < 2; ni++) {
            float r0[4] = {rb[ni][0].x, rb[ni][0].y, rb[ni][0].z, rb[ni][0].w};
            float r1[4] = {rb[ni][1].x, rb[ni][1].y, rb[ni][1].z, rb[ni][1].w};
            uint32_t hw[4], lw[4];
#pragma unroll
            for (int j = 0; j < 4; j++)
                split2(r0[j], r1[j], hw[j], lw[j]);
            int col = ni*64 + bn4*4;
            *(uint4*)&BH[bkp*BWS + col] = make_uint4(hw[0],hw[1],hw[2],hw[3]);
            *(uint4*)&BL[bkp*BWS + col] = make_uint4(lw[0],lw[1],lw[2],lw[3]);
        }
        __syncthreads();

        if (k0 + 32 < K) {
            int kn = k0 + 32;
#pragma unroll
            for (int i = 0; i < 4; i++) {
                int gm = m0 + arow + i*32;
                ra[i] = (gm < M) ? *(const float4*)&A[(size_t)gm*lda + kn + ac4*4]
                                 : make_float4(0.f,0.f,0.f,0.f);
            }
#pragma unroll
            for (int ni = 0; ni < 2; ni++) {
                int col = n0 + ni*64 + bn4*4;
                rb[ni][0] = *(const float4*)&Bm[(size_t)(kn + 2*bkp  )*ldb + col];
                rb[ni][1] = *(const float4*)&Bm[(size_t)(kn + 2*bkp+1)*ldb + col];
            }
        }

#pragma unroll
        for (int kk = 0; kk < 2; kk++) {
            int ko = kk*8;
            uint32_t ah[4][4], al[4][4];
#pragma unroll
            for (int mt = 0; mt < 4; mt++) {
                int r = warpM*64 + mt*16 + g;
                ah[mt][0] = AH[ r   *AWS + ko + c];
                ah[mt][1] = AH[(r+8)*AWS + ko + c];
                ah[mt][2] = AH[ r   *AWS + ko + c + 4];
                ah[mt][3] = AH[(r+8)*AWS + ko + c + 4];
                al[mt][0] = AL[ r   *AWS + ko + c];
                al[mt][1] = AL[(r+8)*AWS + ko + c];
                al[mt][2] = AL[ r   *AWS + ko + c + 4];
                al[mt][3] = AL[(r+8)*AWS + ko + c + 4];
            }
#pragma unroll
            for (int nt = 0; nt < 4; nt++) {
                int ncol = warpN*32 + nt*8 + g;
                uint32_t bh[2], bl[2];
                bh[0] = BH[(ko + c    )*BWS + ncol];
                bh[1] = BH[(ko + c + 4)*BWS + ncol];
                bl[0] = BL[(ko + c    )*BWS + ncol];
                bl[1] = BL[(ko + c + 4)*BWS + ncol];
#pragma unroll
                for (int mt = 0; mt < 4; mt++) {
                    mma_f16(acc[mt][nt], ah[mt], bl);
                    mma_f16(acc[mt][nt], al[mt], bh);
                    mma_f16(acc[mt][nt], ah[mt], bh);
                }
            }
        }
        p ^= 1;
    }

#pragma unroll
    for (int mt = 0; mt < 4; mt++) {
#pragma unroll
        for (int nt = 0; nt < 4; nt++) {
            int r0  = m0 + warpM*64 + mt*16 + g;
            int col = n0 + warpN*32 + nt*8 + 2*c;
#pragma unroll
            for (int half = 0; half < 2; half++) {
                int gm = r0 + half*8;
                if (gm >= M) continue;
#pragma unroll
                for (int jj = 0; jj < 2; jj++) {
                    int gn = col + jj;
                    float v = acc[mt][nt][half*2 + jj] + bias[gn];
                    float* cp = &C[(size_t)gm*ldc + gn];
                    if (EPI == 1) v = 0.5f*v*(1.f + erff(v*0.70710678118654752f));
                    if (EPI == 2) v += *cp;
                    *cp = v;
                }
            }
        }
    }
}

// ==================== FP16x3 GEMM, 128x64 tile (QKV) ======================
#define QAWS 20
#define QBWS 72
#define QA_ST (128*QAWS)
#define QB_ST (16*QBWS)
#define QOFF_AH 0
#define QOFF_AL (2*QA_ST)
#define QOFF_BH (4*QA_ST)
#define QOFF_BL (4*QA_ST + 2*QB_ST)
#define QGEMM_WORDS (4*QA_ST + 4*QB_ST)
#define QGEMM_SMEM (QGEMM_WORDS*4)

__device__ __forceinline__ void gemm64_tile(
    const float* __restrict__ A, int lda,
    const float* __restrict__ Bm, int ldb,
    const float* __restrict__ bias,
    float* __restrict__ C, int ldc,
    int M, int K, int m0, int n0)
{
    extern __shared__ uint32_t smw[];

    int tid  = threadIdx.x;
    int lane = tid & 31, wid = tid >> 5;
    int warpM = wid >> 1, warpN = wid & 1;
    int g = lane >> 2, c = lane & 3;

    int arow = tid >> 3, ac4 = tid & 7;
    int bp   = tid >> 4, bc4 = tid & 15;

    float acc[2][4][4] = {};
    float4 ra[4], rb0, rb1;

#pragma unroll
    for (int i = 0; i < 4; i++) {
        int gm = m0 + arow + i*32;
        ra[i] = (gm < M) ? *(const float4*)&A[(size_t)gm*lda + ac4*4]
                         : make_float4(0.f,0.f,0.f,0.f);
    }
    rb0 = *(const float4*)&Bm[(size_t)(2*bp  )*ldb + n0 + bc4*4];
    rb1 = *(const float4*)&Bm[(size_t)(2*bp+1)*ldb + n0 + bc4*4];

    int p = 0;
    for (int k0 = 0; k0 < K; k0 += 32) {
        uint32_t* AH = smw + QOFF_AH + p*QA_ST;
        uint32_t* AL = smw + QOFF_AL + p*QA_ST;
        uint32_t* BH = smw + QOFF_BH + p*QB_ST;
        uint32_t* BL = smw + QOFF_BL + p*QB_ST;
#pragma unroll
        for (int i = 0; i < 4; i++) {
            int row = arow + i*32;
            uint32_t h0,h1,l0,l1;
            split2(ra[i].x, ra[i].y, h0, l0);
            split2(ra[i].z, ra[i].w, h1, l1);
            *(uint2*)&AH[row*QAWS + ac4*2] = make_uint2(h0, h1);
            *(uint2*)&AL[row*QAWS + ac4*2] = make_uint2(l0, l1);
        }
        {
            float r0[4] = {rb0.x, rb0.y, rb0.z, rb0.w};
            float r1[4] = {rb1.x, rb1.y, rb1.z, rb1.w};
            uint32_t hw[4], lw[4];
#pragma unroll
            for (int j = 0; j < 4; j++)
                split2(r0[j], r1[j], hw[j], lw[j]);
            *(uint4*)&BH[bp*QBWS + bc4*4] = make_uint4(hw[0],hw[1],hw[2],hw[3]);
            *(uint4*)&BL[bp*QBWS + bc4*4] = make_uint4(lw[0],lw[1],lw[2],lw[3]);
        }
        __syncthreads();

        if (k0 + 32 < K) {
            int kn = k0 + 32;
#pragma unroll
            for (int i = 0; i < 4; i++) {
                int gm = m0 + arow + i*32;
                ra[i] = (gm < M) ? *(const float4*)&A[(size_t)gm*lda + kn + ac4*4]
                                 : make_float4(0.f,0.f,0.f,0.f);
            }
            rb0 = *(const float4*)&Bm[(size_t)(kn + 2*bp  )*ldb + n0 + bc4*4];
            rb1 = *(const float4*)&Bm[(size_t)(kn + 2*bp+1)*ldb + n0 + bc4*4];
        }

#pragma unroll
        for (int kk = 0; kk < 2; kk++) {
            int ko = kk*8;
            uint32_t ah[2][4], al[2][4];
#pragma unroll
            for (int mt = 0; mt < 2; mt++) {
                int r = warpM*32 + mt*16 + g;
                ah[mt][0] = AH[ r   *QAWS + ko + c];
                ah[mt][1] = AH[(r+8)*QAWS + ko + c];
                ah[mt][2] = AH[ r   *QAWS + ko + c + 4];
                ah[mt][3] = AH[(r+8)*QAWS + ko + c + 4];
                al[mt][0] = AL[ r   *QAWS + ko + c];
                al[mt][1] = AL[(r+8)*QAWS + ko + c];
                al[mt][2] = AL[ r   *QAWS + ko + c + 4];
                al[mt][3] = AL[(r+8)*QAWS + ko + c + 4];
            }
            uint32_t bh[4][2], bl[4][2];
#pragma unroll
            for (int nt = 0; nt < 4; nt++) {
                int ncol = warpN*32 + nt*8 + g;
                bh[nt][0] = BH[(ko + c    )*QBWS + ncol];
                bh[nt][1] = BH[(ko + c + 4)*QBWS + ncol];
                bl[nt][0] = BL[(ko + c    )*QBWS + ncol];
                bl[nt][1] = BL[(ko + c + 4)*QBWS + ncol];
            }
#pragma unroll
            for (int mt = 0; mt < 2; mt++)
#pragma unroll
                for (int nt = 0; nt < 4; nt++) {
                    mma_f16(acc[mt][nt], ah[mt], bl[nt]);
                    mma_f16(acc[mt][nt], al[mt], bh[nt]);
                    mma_f16(acc[mt][nt], ah[mt], bh[nt]);
                }
        }
        p ^= 1;
    }

#pragma unroll
    for (int mt = 0; mt < 2; mt++) {
#pragma unroll
        for (int nt = 0; nt < 4; nt++) {
            int r0  = m0 + warpM*32 + mt*16 + g;
            int col = n0 + warpN*32 + nt*8 + 2*c;
#pragma unroll
            for (int half = 0; half < 2; half++) {
                int gm = r0 + half*8;
                if (gm >= M) continue;
#pragma unroll
                for (int jj = 0; jj < 2; jj++) {
                    int gn = col + jj;
                    float v = acc[mt][nt][half*2 + jj] + bias[gn];
                    C[(size_t)gm*ldc + gn] = v;
                }
            }
        }
    }
}

__global__ __launch_bounds__(256) void qkv_mma_kernel(
    const float* __restrict__ Wq, const float* __restrict__ bq,
    const float* __restrict__ Wk, const float* __restrict__ bk,
    const float* __restrict__ Wv, const float* __restrict__ bv,
    int layer)
{
    int z = blockIdx.z;
    int h = z % NHD, t = z / NHD;
    const float* W; const float* bi; float* C;
    if (t == 0)      { W = Wq; bi = bq; C = g_Q; }
    else if (t == 1) { W = Wk; bi = bk; C = g_K; }
    else             { W = Wv; bi = bv; C = g_V; }
    size_t off = (size_t)layer*NHD + h;
    gemm64_tile(g_H + h*HD, DIM,
                W + off*HD*HD, HD,
                bi + off*HD,
                C + h*HD, DIM,
                NTOK, HD, blockIdx.y*128, 0);
}

// -------------------- layernorm ------------------------------------------
__global__ __launch_bounds__(256) void ln_kernel(
    const float* __restrict__ X, float* __restrict__ H,
    const float* __restrict__ gw, const float* __restrict__ bw)
{
    __shared__ float rs[8], rq[8];
    int row = blockIdx.x, tid = threadIdx.x;
    int lane = tid & 31, wid = tid >> 5;
    const float* x = X + (size_t)row*DIM;
    float v0 = x[tid], v1 = x[tid+256], v2 = x[tid+512];
    float s = v0+v1+v2;
    float q = v0*v0 + v1*v1 + v2*v2;
#pragma unroll
    for (int o = 16; o; o >>= 1) {
        s += __shfl_xor_sync(0xffffffffu, s, o);
        q += __shfl_xor_sync(0xffffffffu, q, o);
    }
    if (lane == 0) { rs[wid] = s; rq[wid] = q; }
    __syncthreads();
    if (tid == 0) {
        float ts = 0.f, tq = 0.f;
        for (int w = 0; w < 8; w++) { ts += rs[w]; tq += rq[w]; }
        rs[0] = ts; rq[0] = tq;
    }
    __syncthreads();
    float mean = rs[0]*(1.0f/DIM);
    float var  = rq[0]*(1.0f/DIM) - mean*mean;
    float inv  = rsqrtf(var + 1e-5f);
    float* hrow = H + (size_t)row*DIM;
    hrow[tid]     = (v0-mean)*inv*gw[tid]     + bw[tid];
    hrow[tid+256] = (v1-mean)*inv*gw[tid+256] + bw[tid+256];
    hrow[tid+512] = (v2-mean)*inv*gw[tid+512] + bw[tid+512];
}

// ==================== MMA attention (FP16x3) ==============================
// One block per (b,h), 256 threads (8 warps). All of K,V resident as hi/lo
// fp16 smem tiles; queries processed in 4 chunks of 64 rows.
// Warp w: mtile = w>>1 (16 rows), nhalf = w&1.
// Word-layout strides (uint32 words): Q rows 36, K kp-rows 216, V kp-rows 72,
// S rows 108 — all verified conflict-free vs the m16n8k16 fragment patterns.

#define AT_KH 0
#define AT_KL 6912
#define AT_VH 13824
#define AT_VL 21312
#define AT_QH 28800
#define AT_QL 31104
#define AT_SH 33408
#define AT_SL 40320
#define AT_RM 47232
#define AT_RS 47360
#define AT_WORDS 47488
#define AT_SMEM (AT_WORDS*4)   // 189952 bytes

__global__ __launch_bounds__(256) void attn_mma_kernel(
    const float* __restrict__ Q, const float* __restrict__ K,
    const float* __restrict__ V, float* __restrict__ X)
{
    extern __shared__ uint32_t sw[];
    int tid = threadIdx.x;
    int lane = tid & 31, wid = tid >> 5;
    int g = lane >> 2, c = lane & 3;
    int b = blockIdx.x / NHD, h = blockIdx.x % NHD;
    size_t base = (size_t)b*SEQ*DIM + (size_t)h*HD;

    // ---- K: [hd-pair kp 0..31][token n 0..207] ----
    for (int idx = tid; idx < 208*32; idx += 256) {
        int kp = idx & 31, n = idx >> 5;
        float2 kv = (n < SEQ) ? *(const float2*)&K[base + (size_t)n*DIM + 2*kp]
                              : make_float2(0.f, 0.f);
        uint32_t hw, lw; split2(kv.x, kv.y, hw, lw);
        sw[AT_KH + kp*216 + n] = hw;
        sw[AT_KL + kp*216 + n] = lw;
    }
    // ---- V: [token-pair kp 0..103][hd n 0..63] ----
    for (int idx = tid; idx < 104*64; idx += 256) {
        int n = idx & 63, kp = idx >> 6;
        int t0 = 2*kp, t1 = 2*kp + 1;
        float v0 = (t0 < SEQ) ? V[base + (size_t)t0*DIM + n] : 0.f;
        float v1 = (t1 < SEQ) ? V[base + (size_t)t1*DIM + n] : 0.f;
        uint32_t hw, lw; split2(v0, v1, hw, lw);
        sw[AT_VH + kp*72 + n] = hw;
        sw[AT_VL + kp*72 + n] = lw;
    }
    __syncthreads();

    int mt = wid >> 1, nh = wid & 1;
    int r = mt*16 + g;

    for (int ch = 0; ch < 4; ch++) {
        int q0 = ch*64;
        // ---- Q chunk: rows 0..63, scaled by 1/8 (exact) ----
        for (int idx = tid; idx < 64*32; idx += 256) {
            int kp = idx & 31, qr = idx >> 5;
            int qrow = q0 + qr;
            float2 qv = (qrow < SEQ) ? *(const float2*)&Q[base + (size_t)qrow*DIM + 2*kp]
                                     : make_float2(0.f, 0.f);
            uint32_t hw, lw; split2(qv.x*0.125f, qv.y*0.125f, hw, lw);
            sw[AT_QH + qr*36 + kp] = hw;
            sw[AT_QL + qr*36 + kp] = lw;
        }
        __syncthreads();

        // ---- QK^T: warp computes 16 rows x 104 cols (13 n8 tiles) ----
        float sc[13][4];
#pragma unroll
        for (int nt = 0; nt < 13; nt++)
#pragma unroll
            for (int i = 0; i < 4; i++) sc[nt][i] = 0.f;

#pragma unroll
        for (int kk = 0; kk < 4; kk++) {
            int ko = kk*8;
            uint32_t ah[4], al[4];
            ah[0] = sw[AT_QH +  r   *36 + ko + c];
            ah[1] = sw[AT_QH + (r+8)*36 + ko + c];
            ah[2] = sw[AT_QH +  r   *36 + ko + c + 4];
            ah[3] = sw[AT_QH + (r+8)*36 + ko + c + 4];
            al[0] = sw[AT_QL +  r   *36 + ko + c];
            al[1] = sw[AT_QL + (r+8)*36 + ko + c];
            al[2] = sw[AT_QL +  r   *36 + ko + c + 4];
            al[3] = sw[AT_QL + (r+8)*36 + ko + c + 4];
#pragma unroll
            for (int nt = 0; nt < 13; nt++) {
                int ncol = nh*104 + nt*8 + g;
                uint32_t bh[2], bl[2];
                bh[0] = sw[AT_KH + (ko + c    )*216 + ncol];
                bh[1] = sw[AT_KH + (ko + c + 4)*216 + ncol];
                bl[0] = sw[AT_KL + (ko + c    )*216 + ncol];
                bl[1] = sw[AT_KL + (ko + c + 4)*216 + ncol];
                mma_f16(sc[nt], ah, bl);
                mma_f16(sc[nt], al, bh);
                mma_f16(sc[nt], ah, bh);
            }
        }

        // ---- mask padded key columns ----
#pragma unroll
        for (int nt = 0; nt < 13; nt++) {
            int col = nh*104 + nt*8 + 2*c;
            if (col     > 196) { sc[nt][0] = -1e30f; sc[nt][2] = -1e30f; }
            if (col + 1 > 196) { sc[nt][1] = -1e30f; sc[nt][3] = -1e30f; }
        }

        // ---- rowwise max (partial within warp, combined across warp pair) --
        float m0 = -1e30f, m1 = -1e30f;
#pragma unroll
        for (int nt = 0; nt < 13; nt++) {
            m0 = fmaxf(m0, fmaxf(sc[nt][0], sc[nt][1]));
            m1 = fmaxf(m1, fmaxf(sc[nt][2], sc[nt][3]));
        }
        m0 = fmaxf(m0, __shfl_xor_sync(0xffffffffu, m0, 1));
        m0 = fmaxf(m0, __shfl_xor_sync(0xffffffffu, m0, 2));
        m1 = fmaxf(m1, __shfl_xor_sync(0xffffffffu, m1, 1));
        m1 = fmaxf(m1, __shfl_xor_sync(0xffffffffu, m1, 2));
        if (c == 0) {
            sw[AT_RM + wid*16 + g    ] = __float_as_uint(m0);
            sw[AT_RM + wid*16 + g + 8] = __float_as_uint(m1);
        }
        __syncthreads();
        float M0 = fmaxf(__uint_as_float(sw[AT_RM + wid*16 + g]),
                         __uint_as_float(sw[AT_RM + (wid^1)*16 + g]));
        float M1 = fmaxf(__uint_as_float(sw[AT_RM + wid*16 + g + 8]),
                         __uint_as_float(sw[AT_RM + (wid^1)*16 + g + 8]));

        // ---- exp, partial sums, store S (hi/lo, A-operand layout) ----
        float s0 = 0.f, s1 = 0.f;
#pragma unroll
        for (int nt = 0; nt < 13; nt++) {
            float e0 = __expf(sc[nt][0] - M0);
            float e1 = __expf(sc[nt][1] - M0);
            float e2 = __expf(sc[nt][2] - M1);
            float e3 = __expf(sc[nt][3] - M1);
            s0 += e0 + e1;
            s1 += e2 + e3;
            int kp = nh*52 + nt*4 + c;
            uint32_t hw, lw;
            split2(e0, e1, hw, lw);
            sw[AT_SH +  r   *108 + kp] = hw;
            sw[AT_SL +  r   *108 + kp] = lw;
            split2(e2, e3, hw, lw);
            sw[AT_SH + (r+8)*108 + kp] = hw;
            sw[AT_SL + (r+8)*108 + kp] = lw;
        }
        s0 += __shfl_xor_sync(0xffffffffu, s0, 1);
        s0 += __shfl_xor_sync(0xffffffffu, s0, 2);
        s1 += __shfl_xor_sync(0xffffffffu, s1, 1);
        s1 += __shfl_xor_sync(0xffffffffu, s1, 2);
        if (c == 0) {
            sw[AT_RS + wid*16 + g    ] = __float_as_uint(s0);
            sw[AT_RS + wid*16 + g + 8] = __float_as_uint(s1);
        }
        __syncthreads();
        float inv0 = 1.f / (__uint_as_float(sw[AT_RS + wid*16 + g]) +
                            __uint_as_float(sw[AT_RS + (wid^1)*16 + g]));
        float inv1 = 1.f / (__uint_as_float(sw[AT_RS + wid*16 + g + 8]) +
                            __uint_as_float(sw[AT_RS + (wid^1)*16 + g + 8]));

        // ---- AV: warp computes 16 rows x 32 cols (4 n8 tiles) ----
        float ov[4][4];
#pragma unroll
        for (int nt = 0; nt < 4; nt++)
#pragma unroll
            for (int i = 0; i < 4; i++) ov[nt][i] = 0.f;

#pragma unroll
        for (int kk = 0; kk < 13; kk++) {
            int ko = kk*8;
            uint32_t ah[4], al[4];
            ah[0] = sw[AT_SH +  r   *108 + ko + c];
            ah[1] = sw[AT_SH + (r+8)*108 + ko + c];
            ah[2] = sw[AT_SH +  r   *108 + ko + c + 4];
            ah[3] = sw[AT_SH + (r+8)*108 + ko + c + 4];
            al[0] = sw[AT_SL +  r   *108 + ko + c];
            al[1] = sw[AT_SL + (r+8)*108 + ko + c];
            al[2] = sw[AT_SL +  r   *108 + ko + c + 4];
            al[3] = sw[AT_SL + (r+8)*108 + ko + c + 4];
#pragma unroll
            for (int nt = 0; nt < 4; nt++) {
                int ncol = nh*32 + nt*8 + g;
                uint32_t bh[2], bl[2];
                bh[0] = sw[AT_VH + (ko + c    )*72 + ncol];
                bh[1] = sw[AT_VH + (ko + c + 4)*72 + ncol];
                bl[0] = sw[AT_VL + (ko + c    )*72 + ncol];
                bl[1] = sw[AT_VL + (ko + c + 4)*72 + ncol];
                mma_f16(ov[nt], ah, bl);
                mma_f16(ov[nt], al, bh);
                mma_f16(ov[nt], ah, bh);
            }
        }

        // ---- normalize + fused residual add into X ----
#pragma unroll
        for (int nt = 0; nt < 4; nt++) {
            int col = nh*32 + nt*8 + 2*c;
            int qr = q0 + r;
            if (qr < SEQ) {
                float2* xp = (float2*)&X[base + (size_t)qr*DIM + col];
                float2 xo = *xp;
                xo.x += ov[nt][0]*inv0;
                xo.y += ov[nt][1]*inv0;
                *xp = xo;
            }
            if (qr + 8 < SEQ) {
                float2* xp = (float2*)&X[base + (size_t)(qr+8)*DIM + col];
                float2 xo = *xp;
                xo.x += ov[nt][2]*inv1;
                xo.y += ov[nt][3]*inv1;
                *xp = xo;
            }
        }
        __syncthreads();
    }
}

// -------------------- classifier head + softmax --------------------------
__global__ __launch_bounds__(256) void head_kernel(
    const float* __restrict__ X, const float* __restrict__ Wh,
    const float* __restrict__ bh, float* __restrict__ out)
{
    __shared__ float xr[DIM];
    __shared__ float lg[NCLS];
    __shared__ float red[8];
    int b = blockIdx.x, tid = threadIdx.x;
    int lane = tid & 31, wid = tid >> 5;

    for (int d = tid; d < DIM; d += 256) xr[d] = X[(size_t)b*SEQ*DIM + d];
    __syncthreads();

    for (int n = tid; n < NCLS; n += 256) {
        float a = bh[n];
        for (int k = 0; k < DIM; k++)
            a = fmaf(xr[k], Wh[(size_t)k*NCLS + n], a);
        lg[n] = a;
    }
    __syncthreads();

    float lm = -1e30f;
    for (int n = tid; n < NCLS; n += 256) lm = fmaxf(lm, lg[n]);
#pragma unroll
    for (int o = 16; o; o >>= 1) lm = fmaxf(lm, __shfl_xor_sync(0xffffffffu, lm, o));
    if (lane == 0) red[wid] = lm;
    __syncthreads();
    if (tid == 0) {
        float m = red[0];
        for (int w = 1; w < 8; w++) m = fmaxf(m, red[w]);
        red[0] = m;
    }
    __syncthreads();
    float mx = red[0];

    float ls = 0.f;
    for (int n = tid; n < NCLS; n += 256) {
        float e = expf(lg[n] - mx);
        lg[n] = e;
        ls += e;
    }
#pragma unroll
    for (int o = 16; o; o >>= 1) ls += __shfl_xor_sync(0xffffffffu, ls, o);
    __syncthreads();
    if (lane == 0) red[wid] = ls;
    __syncthreads();
    if (tid == 0) {
        float s2 = 0.f;
        for (int w = 0; w < 8; w++) s2 += red[w];
        red[0] = s2;
    }
    __syncthreads();
    float inv = 1.f / red[0];
    for (int n = tid; n < NCLS; n += 256)
        out[(size_t)b*NCLS + n] = lg[n]*inv;
}

// -------------------- launch ---------------------------------------------
extern "C" void kernel_launch(void* const* d_in, const int* in_sizes, int n_in,
                              void* d_out, int out_size)
{
    (void)in_sizes; (void)n_in; (void)out_size;
    const float* images = (const float*)d_in[0];
    const float* Wp     = (const float*)d_in[1];
    const float* bp     = (const float*)d_in[2];
    const float* cls    = (const float*)d_in[3];
    const float* pos    = (const float*)d_in[4];
    const float* ln1_g  = (const float*)d_in[5];
    const float* ln1_b  = (const float*)d_in[6];
    const float* Wq     = (const float*)d_in[7];
    const float* bq     = (const float*)d_in[8];
    const float* Wk     = (const float*)d_in[9];
    const float* bk     = (const float*)d_in[10];
    const float* Wv     = (const float*)d_in[11];
    const float* bv     = (const float*)d_in[12];
    const float* ln2_g  = (const float*)d_in[13];
    const float* ln2_b  = (const float*)d_in[14];
    const float* W1     = (const float*)d_in[15];
    const float* b1     = (const float*)d_in[16];
    const float* W2     = (const float*)d_in[17];
    const float* b2     = (const float*)d_in[18];
    const float* Wh     = (const float*)d_in[19];
    const float* bh     = (const float*)d_in[20];
    float* out = (float*)d_out;

    float *pA, *pH, *pX, *pQ, *pK, *pV, *pU;
    cudaGetSymbolAddress((void**)&pA, g_A);
    cudaGetSymbolAddress((void**)&pH, g_H);
    cudaGetSymbolAddress((void**)&pX, g_X);
    cudaGetSymbolAddress((void**)&pQ, g_Q);
    cudaGetSymbolAddress((void**)&pK, g_K);
    cudaGetSymbolAddress((void**)&pV, g_V);
    cudaGetSymbolAddress((void**)&pU, g_U);

    cudaFuncSetAttribute(gemm128_kernel<0>,
        cudaFuncAttributeMaxDynamicSharedMemorySize, G128_SMEM);
    cudaFuncSetAttribute(gemm128_kernel<1>,
        cudaFuncAttributeMaxDynamicSharedMemorySize, G128_SMEM);
    cudaFuncSetAttribute(gemm128_kernel<2>,
        cudaFuncAttributeMaxDynamicSharedMemorySize, G128_SMEM);
    cudaFuncSetAttribute(qkv_mma_kernel,
        cudaFuncAttributeMaxDynamicSharedMemorySize, QGEMM_SMEM);
    cudaFuncSetAttribute(attn_mma_kernel,
        cudaFuncAttributeMaxDynamicSharedMemorySize, AT_SMEM);

    // Patch embed: (6272 x 768) @ (768 x 768)
    patchify_kernel<<<(BB*NPAT*DIM + 255)/256, 256>>>(images);
    gemm128_kernel<0><<<dim3(DIM/128, (BB*NPAT+127)/128), 256, G128_SMEM>>>(
        pA, DIM, Wp, DIM, bp, pH, DIM, BB*NPAT, DIM);
    assemble_kernel<<<(NTOK*DIM + 255)/256, 256>>>(cls, pos);

    for (int l = 0; l < NL; l++) {
        ln_kernel<<<NTOK, 256>>>(pX, pH, ln1_g + l*DIM, ln1_b + l*DIM);
        qkv_mma_kernel<<<dim3(1, MT128, NHD*3), 256, QGEMM_SMEM>>>(
            Wq, bq, Wk, bk, Wv, bv, l);
        attn_mma_kernel<<<BB*NHD, 256, AT_SMEM>>>(pQ, pK, pV, pX);
        ln_kernel<<<NTOK, 256>>>(pX, pH, ln2_g + l*DIM, ln2_b + l*DIM);
        gemm128_kernel<1><<<dim3(MLPD/128, MT128), 256, G128_SMEM>>>(
            pH, DIM, W1 + (size_t)l*DIM*MLPD, MLPD, b1 + (size_t)l*MLPD,
            pU, MLPD, NTOK, DIM);
        gemm128_kernel<2><<<dim3(DIM/128, MT128), 256, G128_SMEM>>>(
            pU, MLPD, W2 + (size_t)l*MLPD*DIM, DIM, b2 + (size_t)l*DIM,
            pX, DIM, NTOK, MLPD);
    }

    head_kernel<<<BB, 256>>>(pX, Wh, bh, out);
}